// round 16
// baseline (speedup 1.0000x reference)
#include <cuda_runtime.h>
#include <cuda_fp16.h>
#include <cstdint>
#include <math.h>

#define B_  8
#define L_  4096
#define D_  512
#define H_  8
#define CH  64
#define O3  1536

// ---------------- scratch (__device__ globals; no allocs allowed) ----------
__device__ float g_ctxp[64 * 8 * 64 * 64];                     // [bh][split][d][e]
__device__ __half g_Wh[(size_t)O3 * D_];                       // W fp16
__device__ __half g_xh[(size_t)B_ * L_ * D_];                  // x fp16
__device__ __half g_qh[(size_t)B_ * L_ * D_];                  // q fp16 [b][l][c]
__device__ __half g_kh[(size_t)B_ * D_ * L_];                  // k fp16 [b][row][L]
__device__ __half g_vh[(size_t)B_ * D_ * L_];                  // v fp16 [b][row][L]
__device__ __half g_Mh[(size_t)B_ * D_ * D_];                  // M fp16

// ---------------- PTX helpers ---------------------------------------------
__device__ __forceinline__ uint32_t smem_u32(const void* p) {
    uint32_t a;
    asm("{ .reg .u64 t; cvta.to.shared.u64 t, %1; cvt.u32.u64 %0, t; }" : "=r"(a) : "l"(p));
    return a;
}
#define SWZ128(b) ((b) ^ (((b) >> 3) & 0x70))

__device__ __forceinline__ void cp16(uint32_t dst, const void* src) {
    asm volatile("cp.async.cg.shared.global [%0], [%1], 16;" :: "r"(dst), "l"(src));
}
#define CP_COMMIT() asm volatile("cp.async.commit_group;")

__device__ __forceinline__ void ldsm_x4(uint32_t r[4], uint32_t a) {
    asm volatile("ldmatrix.sync.aligned.m8n8.x4.shared.b16 {%0,%1,%2,%3}, [%4];"
                 : "=r"(r[0]), "=r"(r[1]), "=r"(r[2]), "=r"(r[3]) : "r"(a));
}
__device__ __forceinline__ void mma_f16(float d[4], const uint32_t a[4], const uint32_t b[2]) {
    asm volatile("mma.sync.aligned.m16n8k16.row.col.f32.f16.f16.f32 "
                 "{%0,%1,%2,%3}, {%4,%5,%6,%7}, {%8,%9}, {%0,%1,%2,%3};"
                 : "+f"(d[0]), "+f"(d[1]), "+f"(d[2]), "+f"(d[3])
                 : "r"(a[0]), "r"(a[1]), "r"(a[2]), "r"(a[3]), "r"(b[0]), "r"(b[1]));
}

// ---------------- Kernel: fp32 -> fp16 (with element-quad offset) ----------
__global__ __launch_bounds__(256)
void k_split(const float* __restrict__ src, int which, int n4, int off) {
    int i = blockIdx.x * 256 + threadIdx.x;
    if (i >= n4) return;
    i += off;
    float4 v = ((const float4*)src)[i];
    union { __half h[4]; uint2 u; } ph;
    ph.h[0] = __float2half(v.x); ph.h[1] = __float2half(v.y);
    ph.h[2] = __float2half(v.z); ph.h[3] = __float2half(v.w);
    __half* dst = which ? g_Wh : g_xh;
    *(uint2*)(dst + (size_t)i * 4) = ph.u;
}

// ---------------- mma.sync fp16 GEMM, 64x64 warp tiles, frag pipeline ------
// D[m,n] = sum_k A[m,k]*B[n,k]; fp16 x fp16 -> fp32 accum.
// CTA 128x128, 4 warps (2m x 2n), warp tile 64x64, K-chunk 64, 3-stage
// cp.async, one barrier per chunk, double-buffered ldmatrix fragments
// (slice sl+1 loads overlap slice sl MMAs).
// mode 0: qkv (A=W, B=x; m0<512 -> fused q-softmax -> g_qh; else fp16 k/v)
// mode 1: out (A=q, B=M; D+bias -> y fp32)
#define STAGE_B  32768
#define SMEM_MM  (3 * STAGE_B)
#define EST      132                               // epilogue smem row stride

__global__ __launch_bounds__(128, 2)
void k_mm(float* __restrict__ Cout, const float* __restrict__ bias, int mode) {
    extern __shared__ char smem[];
    const int tid  = threadIdx.x;
    const int wid  = tid >> 5, lane = tid & 31;
    const int wm   = wid & 1;          // m offset wm*64
    const int wn   = wid >> 1;         // n offset wn*64
    const int b    = blockIdx.z;
    const int m0   = blockIdx.y * 128;
    const int n0   = blockIdx.x * 128;

    const uint32_t smbase = smem_u32(smem);

    const __half *Ah, *Bh;
    if (mode == 0) {
        Ah = g_Wh + (size_t)m0 * D_;
        Bh = g_xh + ((size_t)b * L_ + n0) * D_;
    } else {
        Ah = g_qh + ((size_t)b * L_ + m0) * D_;
        Bh = g_Mh + ((size_t)b * D_ + n0) * D_;
    }

    auto load_stage = [&](int s, int d0) {
        uint32_t base = smbase + s * STAGE_B;
#pragma unroll
        for (int i = 0; i < 16; i++) {
            int id = i * 128 + tid;                // 0..2047
            int pl = id >> 10;                     // 0=A, 1=B
            int r  = (id >> 3) & 127;
            int u  = id & 7;
            const __half* src = (pl ? Bh : Ah) + (size_t)r * D_ + d0 + u * 8;
            cp16(base + pl * 16384 + SWZ128((uint32_t)(r * 128 + u * 16)), src);
        }
        CP_COMMIT();
    };

    float acc[4][8][4];
#pragma unroll
    for (int i = 0; i < 4; i++)
#pragma unroll
        for (int j = 0; j < 8; j++)
#pragma unroll
            for (int k = 0; k < 4; k++) acc[i][j][k] = 0.f;

    // A lanes: rows within warp's 64-row band, unit by lane>>4
    const uint32_t a_row = wm * 64 + (lane & 15);
    const uint32_t a_ub  = (lane >> 4);
    // B lanes (x4, two nt tiles per load): validated R13 mapping
    const uint32_t b_row = wn * 64 + (lane & 7) + ((lane >> 4) << 3);
    const uint32_t b_ub  = (lane >> 3) & 1;

    uint32_t fa[2][4][4], fb[2][4][4];

    load_stage(0, 0);
    load_stage(1, 64);

#pragma unroll
    for (int kc = 0; kc < 8; kc++) {
        const int s = kc % 3;
        if (kc < 7) asm volatile("cp.async.wait_group 1;");
        else        asm volatile("cp.async.wait_group 0;");
        __syncthreads();
        if (kc + 2 < 8) load_stage((kc + 2) % 3, (kc + 2) * 64);

        uint32_t smA = smbase + s * STAGE_B;
        uint32_t smB = smA + 16384;

        // prime slice 0 fragments
#pragma unroll
        for (int mt = 0; mt < 4; mt++)
            ldsm_x4(fa[0][mt], smA + SWZ128((a_row + mt * 16) * 128 + a_ub * 16));
#pragma unroll
        for (int j = 0; j < 4; j++)
            ldsm_x4(fb[0][j], smB + SWZ128((b_row + j * 16) * 128 + b_ub * 16));

#pragma unroll
        for (int sl = 0; sl < 4; sl++) {
            const int cur = sl & 1;
            if (sl < 3) {
                const int nxt = cur ^ 1;
#pragma unroll
                for (int mt = 0; mt < 4; mt++)
                    ldsm_x4(fa[nxt][mt], smA + SWZ128((a_row + mt * 16) * 128 + ((sl + 1) * 2 + a_ub) * 16));
#pragma unroll
                for (int j = 0; j < 4; j++)
                    ldsm_x4(fb[nxt][j], smB + SWZ128((b_row + j * 16) * 128 + ((sl + 1) * 2 + b_ub) * 16));
            }
#pragma unroll
            for (int j = 0; j < 4; j++)
#pragma unroll
                for (int half = 0; half < 2; half++) {
                    const uint32_t* bf = &fb[cur][j][half * 2];
#pragma unroll
                    for (int mt = 0; mt < 4; mt++)
                        mma_f16(acc[mt][j * 2 + half], fa[cur][mt], bf);
                }
        }
    }
    __syncthreads();

    // ---- single-pass full-width epilogue ----
    float* ep = (float*)smem;                      // [128][EST]
    float* inv_s = ep + 128 * EST;                 // [2][128]
    {
        int cb = wn * 64;
#pragma unroll
        for (int mt = 0; mt < 4; mt++)
#pragma unroll
            for (int nt = 0; nt < 8; nt++) {
                int row = wm * 64 + mt * 16 + (lane >> 2);
                int col = cb + nt * 8 + (lane & 3) * 2;
                ep[row * EST + col]           = acc[mt][nt][0];
                ep[row * EST + col + 1]       = acc[mt][nt][1];
                ep[(row + 8) * EST + col]     = acc[mt][nt][2];
                ep[(row + 8) * EST + col + 1] = acc[mt][nt][3];
            }
    }
    __syncthreads();

    if (mode == 0 && m0 < 512) {
        // fused q-softmax over channel dim (rows); 2 heads per tile, 256 cols.
#pragma unroll
        for (int t = 0; t < 2; t++) {
            int task = tid + t * 128;              // 0..255
            int c  = task & 127;
            int r0 = (task >> 7) * 64;
            float mx = -3.0e38f;
#pragma unroll 8
            for (int r = 0; r < 64; r++) mx = fmaxf(mx, ep[(r0 + r) * EST + c]);
            float s = 0.f;
#pragma unroll 8
            for (int r = 0; r < 64; r++) {
                float e = expf(ep[(r0 + r) * EST + c] - mx);
                ep[(r0 + r) * EST + c] = e;
                s += e;
            }
            inv_s[(task >> 7) * 128 + c] = 1.0f / s;
        }
        __syncthreads();
        // write fp16 q transposed: g_qh[b][l = n0+c][channel = m0+mg*4..]
#pragma unroll
        for (int i = 0; i < 32; i++) {
            int id = tid + 128 * i;                // 0..4095
            int c = id >> 5, mg = id & 31;
            float inv = inv_s[(mg >> 4) * 128 + c];
            union { __half h[4]; uint2 u; } ph;
            ph.h[0] = __float2half(ep[(mg * 4 + 0) * EST + c] * inv);
            ph.h[1] = __float2half(ep[(mg * 4 + 1) * EST + c] * inv);
            ph.h[2] = __float2half(ep[(mg * 4 + 2) * EST + c] * inv);
            ph.h[3] = __float2half(ep[(mg * 4 + 3) * EST + c] * inv);
            *(uint2*)(g_qh + ((size_t)b * L_ + n0 + c) * D_ + m0 + mg * 4) = ph.u;
        }
    } else if (mode == 0) {
        // k / v -> fp16 [b][row][L]
        __half* dst = (m0 < 1024)
            ? g_kh + ((size_t)b * D_ + (m0 - 512))  * L_
            : g_vh + ((size_t)b * D_ + (m0 - 1024)) * L_;
#pragma unroll
        for (int i = 0; i < 32; i++) {
            int id = tid + 128 * i;                // 0..4095
            int m = id >> 5, g = id & 31;
            union { __half h[4]; uint2 u; } ph;
            ph.h[0] = __float2half(ep[m * EST + g * 4 + 0]);
            ph.h[1] = __float2half(ep[m * EST + g * 4 + 1]);
            ph.h[2] = __float2half(ep[m * EST + g * 4 + 2]);
            ph.h[3] = __float2half(ep[m * EST + g * 4 + 3]);
            *(uint2*)(dst + (size_t)m * L_ + n0 + g * 4) = ph.u;
        }
    } else {
        float* dst = Cout + ((size_t)b * L_ + m0) * D_;
#pragma unroll
        for (int i = 0; i < 32; i++) {
            int id = tid + 128 * i;
            int m = id >> 5, g = id & 31;
            float4 v;
            v.x = ep[m * EST + g * 4 + 0] + __ldg(bias + n0 + g * 4 + 0);
            v.y = ep[m * EST + g * 4 + 1] + __ldg(bias + n0 + g * 4 + 1);
            v.z = ep[m * EST + g * 4 + 2] + __ldg(bias + n0 + g * 4 + 2);
            v.w = ep[m * EST + g * 4 + 3] + __ldg(bias + n0 + g * 4 + 3);
            *(float4*)(dst + (size_t)m * D_ + n0 + g * 4) = v;
        }
    }
}

// ---------------- softmax over L for k rows (fp16 storage) -----------------
__global__ __launch_bounds__(256)
void k_softmax_rows() {
    const int r = blockIdx.x, b = blockIdx.y;
    __half* row = g_kh + ((size_t)b * D_ + r) * L_;
    const int tid = threadIdx.x;
    __shared__ float red[8], bc[2];

    union { uint4 u; __half2 h2[4]; } v[2];
    float f[16];
    float mx = -3.0e38f;
#pragma unroll
    for (int j = 0; j < 2; j++) {
        v[j].u = ((const uint4*)row)[tid + 256 * j];
#pragma unroll
        for (int q = 0; q < 4; q++) {
            float2 p = __half22float2(v[j].h2[q]);
            f[j * 8 + q * 2]     = p.x;
            f[j * 8 + q * 2 + 1] = p.y;
            mx = fmaxf(mx, fmaxf(p.x, p.y));
        }
    }
#pragma unroll
    for (int o = 16; o; o >>= 1) mx = fmaxf(mx, __shfl_xor_sync(0xffffffffu, mx, o));
    if ((tid & 31) == 0) red[tid >> 5] = mx;
    __syncthreads();
    if (tid < 32) {
        float m2 = (tid < 8) ? red[tid] : -3.0e38f;
#pragma unroll
        for (int o = 4; o; o >>= 1) m2 = fmaxf(m2, __shfl_xor_sync(0xffffffffu, m2, o));
        if (tid == 0) bc[0] = m2;
    }
    __syncthreads();
    const float m = bc[0];

    float s = 0.f;
#pragma unroll
    for (int i = 0; i < 16; i++) { f[i] = expf(f[i] - m); s += f[i]; }
#pragma unroll
    for (int o = 16; o; o >>= 1) s += __shfl_xor_sync(0xffffffffu, s, o);
    if ((tid & 31) == 0) red[tid >> 5] = s;
    __syncthreads();
    if (tid < 32) {
        float s2 = (tid < 8) ? red[tid] : 0.f;
#pragma unroll
        for (int o = 4; o; o >>= 1) s2 += __shfl_xor_sync(0xffffffffu, s2, o);
        if (tid == 0) bc[1] = s2;
    }
    __syncthreads();
    const float inv = 1.0f / bc[1];
#pragma unroll
    for (int j = 0; j < 2; j++) {
#pragma unroll
        for (int q = 0; q < 4; q++)
            v[j].h2[q] = __floats2half2_rn(f[j * 8 + q * 2] * inv, f[j * 8 + q * 2 + 1] * inv);
        ((uint4*)row)[tid + 256 * j] = v[j].u;
    }
}

// ---------------- context partials: ctx[d,e] = sum_n k[d,n] v[e,n] ---------
__global__ __launch_bounds__(256)
void k_ctx() {
    const int bh = blockIdx.x, sp = blockIdx.y;
    const int b = bh >> 3, h = bh & 7;
    const __half* kbase = g_kh + ((size_t)b * D_ + h * CH) * L_;
    const __half* vbase = g_vh + ((size_t)b * D_ + h * CH) * L_;

    __shared__ float ks[64][65];
    __shared__ float vs[64][65];
    const int tid = threadIdx.x;
    const int tx = tid & 15, ty = tid >> 4;

    float acc[4][4];
#pragma unroll
    for (int i = 0; i < 4; i++)
#pragma unroll
        for (int j = 0; j < 4; j++) acc[i][j] = 0.f;

    for (int chn = 0; chn < 8; chn++) {
        int n0 = sp * 512 + chn * 64;
#pragma unroll
        for (int i = 0; i < 4; i++) {
            int id = tid + 256 * i;               // 0..1023
            int arr = id >> 9;                    // 0 = k, 1 = v
            int idx = id & 511;
            int row = idx >> 3, u = idx & 7;
            const __half* src = (arr ? vbase : kbase) + (size_t)row * L_ + n0 + u * 8;
            union { uint4 q; __half2 h2[4]; } t;
            t.q = *(const uint4*)src;
            float* dstrow = (arr ? &vs[0][0] : &ks[0][0]) + row * 65 + u * 8;
#pragma unroll
            for (int qq = 0; qq < 4; qq++) {
                float2 p = __half22float2(t.h2[qq]);
                dstrow[qq * 2]     = p.x;
                dstrow[qq * 2 + 1] = p.y;
            }
        }
        __syncthreads();
#pragma unroll 4
        for (int nn = 0; nn < 64; nn++) {
            float kr[4], vr[4];
#pragma unroll
            for (int i = 0; i < 4; i++) kr[i] = ks[ty * 4 + i][nn];
#pragma unroll
            for (int j = 0; j < 4; j++) vr[j] = vs[tx + 16 * j][nn];
#pragma unroll
            for (int i = 0; i < 4; i++)
#pragma unroll
                for (int j = 0; j < 4; j++) acc[i][j] = fmaf(kr[i], vr[j], acc[i][j]);
        }
        __syncthreads();
    }
    float* out = g_ctxp + (size_t)(bh * 8 + sp) * 4096;
#pragma unroll
    for (int i = 0; i < 4; i++)
#pragma unroll
        for (int j = 0; j < 4; j++)
            out[(size_t)(ty * 4 + i) * 64 + tx + 16 * j] = acc[i][j];
}

// ---------------- reduce ctx + M = Wout-contract, emit fp16 ----------------
__global__ __launch_bounds__(256)
void k_M(const float* __restrict__ Wout) {
    const int bh = blockIdx.x;
    const int b = bh >> 3, h = bh & 7;
    __shared__ float ctxs[64][65];
    const int tid = threadIdx.x;

    for (int e0 = tid; e0 < 4096; e0 += 256) {
        float sum = 0.f;
        const float* p = g_ctxp + (size_t)bh * 8 * 4096 + e0;
#pragma unroll
        for (int s = 0; s < 8; s++) sum += p[(size_t)s * 4096];
        ctxs[e0 >> 6][e0 & 63] = sum;
    }
    __syncthreads();

    const int d = tid & 63, dq = tid >> 6;
    for (int dout = dq; dout < D_; dout += 4) {
        const float* wrow = Wout + (size_t)dout * D_ + h * CH;
        float sum = 0.f;
#pragma unroll
        for (int e = 0; e < CH; e++) sum = fmaf(__ldg(wrow + e), ctxs[d][e], sum);
        g_Mh[(size_t)b * D_ * D_ + (size_t)dout * D_ + h * CH + d] = __float2half(sum);
    }
}

// ---------------------------------------------------------------------------
extern "C" void kernel_launch(void* const* d_in, const int* in_sizes, int n_in,
                              void* d_out, int out_size) {
    const float* x    = (const float*)d_in[0];
    const float* Wqkv = (const float*)d_in[1];
    const float* Wout = (const float*)d_in[2];
    const float* bout = (const float*)d_in[3];
    float* y = (float*)d_out;

    cudaFuncSetAttribute(k_mm, cudaFuncAttributeMaxDynamicSharedMemorySize, SMEM_MM);

    int n4x = B_ * L_ * D_ / 4;
    int n4w = O3 * D_ / 4;
    // x convert split into two launches so qkv k_mm is the 4th launch (ncu target)
    k_split<<<(n4x / 2 + 255) / 256, 256>>>(x, 0, n4x / 2, 0);
    k_split<<<(n4x / 2 + 255) / 256, 256>>>(x, 0, n4x / 2, n4x / 2);
    k_split<<<(n4w + 255) / 256, 256>>>(Wqkv, 1, n4w, 0);

    k_mm<<<dim3(32, 12, B_), 128, SMEM_MM>>>(nullptr, nullptr, 0);    // qkv (4th launch)
    k_softmax_rows<<<dim3(512, B_), 256>>>();
    k_ctx<<<dim3(64, 8), 256>>>();
    k_M<<<64, 256>>>(Wout);
    k_mm<<<dim3(4, 32, B_), 128, SMEM_MM>>>(y, bout, 1);              // out
}

// round 17
// speedup vs baseline: 1.4991x; 1.4991x over previous
#include <cuda_runtime.h>
#include <cuda_fp16.h>
#include <cstdint>
#include <math.h>

#define B_  8
#define L_  4096
#define D_  512
#define H_  8
#define CH  64
#define O3  1536

// ---------------- scratch (__device__ globals; no allocs allowed) ----------
__device__ float g_ctxp[64 * 8 * 64 * 64];                     // [bh][split][d][e]
__device__ __half g_Wh[(size_t)O3 * D_];                       // W fp16
__device__ __half g_xh[(size_t)B_ * L_ * D_];                  // x fp16
__device__ __half g_qh[(size_t)B_ * L_ * D_];                  // q fp16 [b][l][c]
__device__ __half g_kh[(size_t)B_ * D_ * L_];                  // k fp16 [b][row][L]
__device__ __half g_vh[(size_t)B_ * D_ * L_];                  // v fp16 [b][row][L]
__device__ __half g_Mh[(size_t)B_ * D_ * D_];                  // M fp16

// ---------------- PTX helpers ---------------------------------------------
__device__ __forceinline__ uint32_t smem_u32(const void* p) {
    uint32_t a;
    asm("{ .reg .u64 t; cvta.to.shared.u64 t, %1; cvt.u32.u64 %0, t; }" : "=r"(a) : "l"(p));
    return a;
}
#define SWZ128(b) ((b) ^ (((b) >> 3) & 0x70))

__device__ __forceinline__ void cp16(uint32_t dst, const void* src) {
    asm volatile("cp.async.cg.shared.global [%0], [%1], 16;" :: "r"(dst), "l"(src));
}
#define CP_COMMIT() asm volatile("cp.async.commit_group;")

__device__ __forceinline__ void ldsm_x4(uint32_t r[4], uint32_t a) {
    asm volatile("ldmatrix.sync.aligned.m8n8.x4.shared.b16 {%0,%1,%2,%3}, [%4];"
                 : "=r"(r[0]), "=r"(r[1]), "=r"(r[2]), "=r"(r[3]) : "r"(a));
}
__device__ __forceinline__ void mma_f16(float d[4], const uint32_t a[4], const uint32_t b[2]) {
    asm volatile("mma.sync.aligned.m16n8k16.row.col.f32.f16.f16.f32 "
                 "{%0,%1,%2,%3}, {%4,%5,%6,%7}, {%8,%9}, {%0,%1,%2,%3};"
                 : "+f"(d[0]), "+f"(d[1]), "+f"(d[2]), "+f"(d[3])
                 : "r"(a[0]), "r"(a[1]), "r"(a[2]), "r"(a[3]), "r"(b[0]), "r"(b[1]));
}

// ---------------- Kernel: fp32 -> fp16 (x and W fused in one grid) ---------
__global__ __launch_bounds__(256)
void k_split(const float* __restrict__ x, const float* __restrict__ W,
             int n4x, int n4w) {
    int i = blockIdx.x * 256 + threadIdx.x;
    const float* src; __half* dst; int idx;
    if (i < n4x) { src = x; dst = g_xh; idx = i; }
    else if (i < n4x + n4w) { src = W; dst = g_Wh; idx = i - n4x; }
    else return;
    float4 v = ((const float4*)src)[idx];
    union { __half h[4]; uint2 u; } ph;
    ph.h[0] = __float2half(v.x); ph.h[1] = __float2half(v.y);
    ph.h[2] = __float2half(v.z); ph.h[3] = __float2half(v.w);
    *(uint2*)(dst + (size_t)idx * 4) = ph.u;
}

// ---------------- mma.sync fp16 GEMM, 64x64 warp tiles (R15 config) --------
// D[m,n] = sum_k A[m,k]*B[n,k]; fp16 x fp16 -> fp32 accum.
// CTA 128x128, 4 warps (2m x 2n), warp tile 64x64, K-chunk 64, 3-stage
// cp.async, one barrier per chunk.
// mode 0: qkv (A=W, B=x; m0<512 -> fused q-softmax -> g_qh; else fp16 k/v)
// mode 1: out (A=q, B=M; D+bias -> y fp32)
#define STAGE_B  32768
#define SMEM_MM  (3 * STAGE_B)
#define EST      132                               // epilogue smem row stride

__global__ __launch_bounds__(128, 2)
void k_mm(float* __restrict__ Cout, const float* __restrict__ bias, int mode) {
    extern __shared__ char smem[];
    const int tid  = threadIdx.x;
    const int wid  = tid >> 5, lane = tid & 31;
    const int wm   = wid & 1;          // m offset wm*64
    const int wn   = wid >> 1;         // n offset wn*64
    const int b    = blockIdx.z;
    const int m0   = blockIdx.y * 128;
    const int n0   = blockIdx.x * 128;

    const uint32_t smbase = smem_u32(smem);

    const __half *Ah, *Bh;
    if (mode == 0) {
        Ah = g_Wh + (size_t)m0 * D_;
        Bh = g_xh + ((size_t)b * L_ + n0) * D_;
    } else {
        Ah = g_qh + ((size_t)b * L_ + m0) * D_;
        Bh = g_Mh + ((size_t)b * D_ + n0) * D_;
    }

    auto load_stage = [&](int s, int d0) {
        uint32_t base = smbase + s * STAGE_B;
#pragma unroll
        for (int i = 0; i < 16; i++) {
            int id = i * 128 + tid;                // 0..2047
            int pl = id >> 10;                     // 0=A, 1=B
            int r  = (id >> 3) & 127;
            int u  = id & 7;
            const __half* src = (pl ? Bh : Ah) + (size_t)r * D_ + d0 + u * 8;
            cp16(base + pl * 16384 + SWZ128((uint32_t)(r * 128 + u * 16)), src);
        }
        CP_COMMIT();
    };

    float acc[4][8][4];
#pragma unroll
    for (int i = 0; i < 4; i++)
#pragma unroll
        for (int j = 0; j < 8; j++)
#pragma unroll
            for (int k = 0; k < 4; k++) acc[i][j][k] = 0.f;

    // A lanes: rows within warp's 64-row band, unit by lane>>4
    const uint32_t a_row = wm * 64 + (lane & 15);
    const uint32_t a_ub  = (lane >> 4);
    // B lanes (x4, two nt tiles per load): validated R13 mapping
    const uint32_t b_row = wn * 64 + (lane & 7) + ((lane >> 4) << 3);
    const uint32_t b_ub  = (lane >> 3) & 1;

    load_stage(0, 0);
    load_stage(1, 64);

#pragma unroll
    for (int kc = 0; kc < 8; kc++) {
        const int s = kc % 3;
        if (kc < 7) asm volatile("cp.async.wait_group 1;");
        else        asm volatile("cp.async.wait_group 0;");
        __syncthreads();
        if (kc + 2 < 8) load_stage((kc + 2) % 3, (kc + 2) * 64);

        uint32_t smA = smbase + s * STAGE_B;
        uint32_t smB = smA + 16384;
#pragma unroll
        for (int sl = 0; sl < 4; sl++) {
            uint32_t ah[4][4];
#pragma unroll
            for (int mt = 0; mt < 4; mt++)
                ldsm_x4(ah[mt], smA + SWZ128((a_row + mt * 16) * 128 + (sl * 2 + a_ub) * 16));
#pragma unroll
            for (int j = 0; j < 4; j++) {          // 4 B pairs -> nt = 2j, 2j+1
                uint32_t bb[4];
                ldsm_x4(bb, smB + SWZ128((b_row + j * 16) * 128 + (sl * 2 + b_ub) * 16));
#pragma unroll
                for (int half = 0; half < 2; half++) {
                    const uint32_t* bf = &bb[half * 2];
#pragma unroll
                    for (int mt = 0; mt < 4; mt++)
                        mma_f16(acc[mt][j * 2 + half], ah[mt], bf);
                }
            }
        }
    }
    __syncthreads();

    // ---- single-pass full-width epilogue ----
    float* ep = (float*)smem;                      // [128][EST]
    float* inv_s = ep + 128 * EST;                 // [2][128]
    {
        int cb = wn * 64;
#pragma unroll
        for (int mt = 0; mt < 4; mt++)
#pragma unroll
            for (int nt = 0; nt < 8; nt++) {
                int row = wm * 64 + mt * 16 + (lane >> 2);
                int col = cb + nt * 8 + (lane & 3) * 2;
                ep[row * EST + col]           = acc[mt][nt][0];
                ep[row * EST + col + 1]       = acc[mt][nt][1];
                ep[(row + 8) * EST + col]     = acc[mt][nt][2];
                ep[(row + 8) * EST + col + 1] = acc[mt][nt][3];
            }
    }
    __syncthreads();

    if (mode == 0 && m0 < 512) {
        // fused q-softmax over channel dim (rows); 2 heads per tile, 256 cols.
#pragma unroll
        for (int t = 0; t < 2; t++) {
            int task = tid + t * 128;              // 0..255
            int c  = task & 127;
            int r0 = (task >> 7) * 64;
            float mx = -3.0e38f;
#pragma unroll 8
            for (int r = 0; r < 64; r++) mx = fmaxf(mx, ep[(r0 + r) * EST + c]);
            float s = 0.f;
#pragma unroll 8
            for (int r = 0; r < 64; r++) {
                float e = __expf(ep[(r0 + r) * EST + c] - mx);
                ep[(r0 + r) * EST + c] = e;
                s += e;
            }
            inv_s[(task >> 7) * 128 + c] = 1.0f / s;
        }
        __syncthreads();
        // write fp16 q transposed: g_qh[b][l = n0+c][channel = m0+mg*4..]
#pragma unroll
        for (int i = 0; i < 32; i++) {
            int id = tid + 128 * i;                // 0..4095
            int c = id >> 5, mg = id & 31;
            float inv = inv_s[(mg >> 4) * 128 + c];
            union { __half h[4]; uint2 u; } ph;
            ph.h[0] = __float2half(ep[(mg * 4 + 0) * EST + c] * inv);
            ph.h[1] = __float2half(ep[(mg * 4 + 1) * EST + c] * inv);
            ph.h[2] = __float2half(ep[(mg * 4 + 2) * EST + c] * inv);
            ph.h[3] = __float2half(ep[(mg * 4 + 3) * EST + c] * inv);
            *(uint2*)(g_qh + ((size_t)b * L_ + n0 + c) * D_ + m0 + mg * 4) = ph.u;
        }
    } else if (mode == 0) {
        // k / v -> fp16 [b][row][L]
        __half* dst = (m0 < 1024)
            ? g_kh + ((size_t)b * D_ + (m0 - 512))  * L_
            : g_vh + ((size_t)b * D_ + (m0 - 1024)) * L_;
#pragma unroll
        for (int i = 0; i < 32; i++) {
            int id = tid + 128 * i;                // 0..4095
            int m = id >> 5, g = id & 31;
            union { __half h[4]; uint2 u; } ph;
            ph.h[0] = __float2half(ep[m * EST + g * 4 + 0]);
            ph.h[1] = __float2half(ep[m * EST + g * 4 + 1]);
            ph.h[2] = __float2half(ep[m * EST + g * 4 + 2]);
            ph.h[3] = __float2half(ep[m * EST + g * 4 + 3]);
            *(uint2*)(dst + (size_t)m * L_ + n0 + g * 4) = ph.u;
        }
    } else {
        float* dst = Cout + ((size_t)b * L_ + m0) * D_;
#pragma unroll
        for (int i = 0; i < 32; i++) {
            int id = tid + 128 * i;
            int m = id >> 5, g = id & 31;
            float4 v;
            v.x = ep[m * EST + g * 4 + 0] + __ldg(bias + n0 + g * 4 + 0);
            v.y = ep[m * EST + g * 4 + 1] + __ldg(bias + n0 + g * 4 + 1);
            v.z = ep[m * EST + g * 4 + 2] + __ldg(bias + n0 + g * 4 + 2);
            v.w = ep[m * EST + g * 4 + 3] + __ldg(bias + n0 + g * 4 + 3);
            *(float4*)(dst + (size_t)m * D_ + n0 + g * 4) = v;
        }
    }
}

// ---------------- softmax over L for k rows (fp16 storage) -----------------
__global__ __launch_bounds__(256)
void k_softmax_rows() {
    const int r = blockIdx.x, b = blockIdx.y;
    __half* row = g_kh + ((size_t)b * D_ + r) * L_;
    const int tid = threadIdx.x;
    __shared__ float red[8], bc[2];

    union { uint4 u; __half2 h2[4]; } v[2];
    float f[16];
    float mx = -3.0e38f;
#pragma unroll
    for (int j = 0; j < 2; j++) {
        v[j].u = ((const uint4*)row)[tid + 256 * j];
#pragma unroll
        for (int q = 0; q < 4; q++) {
            float2 p = __half22float2(v[j].h2[q]);
            f[j * 8 + q * 2]     = p.x;
            f[j * 8 + q * 2 + 1] = p.y;
            mx = fmaxf(mx, fmaxf(p.x, p.y));
        }
    }
#pragma unroll
    for (int o = 16; o; o >>= 1) mx = fmaxf(mx, __shfl_xor_sync(0xffffffffu, mx, o));
    if ((tid & 31) == 0) red[tid >> 5] = mx;
    __syncthreads();
    if (tid < 32) {
        float m2 = (tid < 8) ? red[tid] : -3.0e38f;
#pragma unroll
        for (int o = 4; o; o >>= 1) m2 = fmaxf(m2, __shfl_xor_sync(0xffffffffu, m2, o));
        if (tid == 0) bc[0] = m2;
    }
    __syncthreads();
    const float m = bc[0];

    float s = 0.f;
#pragma unroll
    for (int i = 0; i < 16; i++) { f[i] = __expf(f[i] - m); s += f[i]; }
#pragma unroll
    for (int o = 16; o; o >>= 1) s += __shfl_xor_sync(0xffffffffu, s, o);
    if ((tid & 31) == 0) red[tid >> 5] = s;
    __syncthreads();
    if (tid < 32) {
        float s2 = (tid < 8) ? red[tid] : 0.f;
#pragma unroll
        for (int o = 4; o; o >>= 1) s2 += __shfl_xor_sync(0xffffffffu, s2, o);
        if (tid == 0) bc[1] = s2;
    }
    __syncthreads();
    const float inv = 1.0f / bc[1];
#pragma unroll
    for (int j = 0; j < 2; j++) {
#pragma unroll
        for (int q = 0; q < 4; q++)
            v[j].h2[q] = __floats2half2_rn(f[j * 8 + q * 2] * inv, f[j * 8 + q * 2 + 1] * inv);
        ((uint4*)row)[tid + 256 * j] = v[j].u;
    }
}

// ---------------- context partials: ctx[d,e] = sum_n k[d,n] v[e,n] ---------
__global__ __launch_bounds__(256)
void k_ctx() {
    const int bh = blockIdx.x, sp = blockIdx.y;
    const int b = bh >> 3, h = bh & 7;
    const __half* kbase = g_kh + ((size_t)b * D_ + h * CH) * L_;
    const __half* vbase = g_vh + ((size_t)b * D_ + h * CH) * L_;

    __shared__ float ks[64][65];
    __shared__ float vs[64][65];
    const int tid = threadIdx.x;
    const int tx = tid & 15, ty = tid >> 4;

    float acc[4][4];
#pragma unroll
    for (int i = 0; i < 4; i++)
#pragma unroll
        for (int j = 0; j < 4; j++) acc[i][j] = 0.f;

    for (int chn = 0; chn < 8; chn++) {
        int n0 = sp * 512 + chn * 64;
#pragma unroll
        for (int i = 0; i < 4; i++) {
            int id = tid + 256 * i;               // 0..1023
            int arr = id >> 9;                    // 0 = k, 1 = v
            int idx = id & 511;
            int row = idx >> 3, u = idx & 7;
            const __half* src = (arr ? vbase : kbase) + (size_t)row * L_ + n0 + u * 8;
            union { uint4 q; __half2 h2[4]; } t;
            t.q = *(const uint4*)src;
            float* dstrow = (arr ? &vs[0][0] : &ks[0][0]) + row * 65 + u * 8;
#pragma unroll
            for (int qq = 0; qq < 4; qq++) {
                float2 p = __half22float2(t.h2[qq]);
                dstrow[qq * 2]     = p.x;
                dstrow[qq * 2 + 1] = p.y;
            }
        }
        __syncthreads();
#pragma unroll 4
        for (int nn = 0; nn < 64; nn++) {
            float kr[4], vr[4];
#pragma unroll
            for (int i = 0; i < 4; i++) kr[i] = ks[ty * 4 + i][nn];
#pragma unroll
            for (int j = 0; j < 4; j++) vr[j] = vs[tx + 16 * j][nn];
#pragma unroll
            for (int i = 0; i < 4; i++)
#pragma unroll
                for (int j = 0; j < 4; j++) acc[i][j] = fmaf(kr[i], vr[j], acc[i][j]);
        }
        __syncthreads();
    }
    float* out = g_ctxp + (size_t)(bh * 8 + sp) * 4096;
#pragma unroll
    for (int i = 0; i < 4; i++)
#pragma unroll
        for (int j = 0; j < 4; j++)
            out[(size_t)(ty * 4 + i) * 64 + tx + 16 * j] = acc[i][j];
}

// ---------------- reduce ctx + M = Wout-contract, emit fp16 ----------------
__global__ __launch_bounds__(256)
void k_M(const float* __restrict__ Wout) {
    const int bh = blockIdx.x;
    const int b = bh >> 3, h = bh & 7;
    __shared__ float ctxs[64][65];
    const int tid = threadIdx.x;

    for (int e0 = tid; e0 < 4096; e0 += 256) {
        float sum = 0.f;
        const float* p = g_ctxp + (size_t)bh * 8 * 4096 + e0;
#pragma unroll
        for (int s = 0; s < 8; s++) sum += p[(size_t)s * 4096];
        ctxs[e0 >> 6][e0 & 63] = sum;
    }
    __syncthreads();

    const int d = tid & 63, dq = tid >> 6;
    for (int dout = dq; dout < D_; dout += 4) {
        const float* wrow = Wout + (size_t)dout * D_ + h * CH;
        float sum = 0.f;
#pragma unroll
        for (int e = 0; e < CH; e++) sum = fmaf(__ldg(wrow + e), ctxs[d][e], sum);
        g_Mh[(size_t)b * D_ * D_ + (size_t)dout * D_ + h * CH + d] = __float2half(sum);
    }
}

// ---------------------------------------------------------------------------
extern "C" void kernel_launch(void* const* d_in, const int* in_sizes, int n_in,
                              void* d_out, int out_size) {
    const float* x    = (const float*)d_in[0];
    const float* Wqkv = (const float*)d_in[1];
    const float* Wout = (const float*)d_in[2];
    const float* bout = (const float*)d_in[3];
    float* y = (float*)d_out;

    cudaFuncSetAttribute(k_mm, cudaFuncAttributeMaxDynamicSharedMemorySize, SMEM_MM);

    int n4x = B_ * L_ * D_ / 4;
    int n4w = O3 * D_ / 4;
    k_split<<<(n4x + n4w + 255) / 256, 256>>>(x, Wqkv, n4x, n4w);

    k_mm<<<dim3(32, 12, B_), 128, SMEM_MM>>>(nullptr, nullptr, 0);    // qkv
    k_softmax_rows<<<dim3(512, B_), 256>>>();
    k_ctx<<<dim3(64, 8), 256>>>();                                    // 4th launch (ncu)
    k_M<<<64, 256>>>(Wout);
    k_mm<<<dim3(4, 32, B_), 128, SMEM_MM>>>(y, bout, 1);              // out
}